// round 16
// baseline (speedup 1.0000x reference)
#include <cuda_runtime.h>
#include <cuda_bf16.h>
#include <cstdint>

// Gather3d: x [1, 128, 16, 128, 128] f32, active_indices [128, 2] i32 in [0,112)
// out [128, 128, 18, 16, 16] f32:
//   out[n, c, T, i, j] = (T < 2) ? 0 : x[0, c, T-2, idx_y[n]+i, idx_x[n]+j]
//
// R15: double-buffered gather -> bulk-async store pipeline.
//   - CTA = (n, 4 channels); two 18 KB smem buffers. While the TMA bulk store
//     of channel k drains, threads gather channel k+1 (wait_group.read <= 1
//     gates buffer reuse). Load engine + async store engine stay concurrently
//     busy inside every CTA instead of only statistically across CTAs.
//   - Zero pad frames (T=0,1) written once into both buffers; bulk stores only
//     READ smem, so they persist across all 4 channels.
//   - Bulk stores carry an L2::evict_first cache hint so the 302 MB write
//     stream drains promptly and stops displacing the read-reuse planes.
//   - Read mapping unchanged (R9): lane=(i,j), warp spans 2 input rows;
//     grid n-inner so all 128 n share each (c,t) plane in L2.

#define CC   128
#define TIN  16
#define TT   18
#define HW   128
#define NN   128
#define BH   16
#define BW   16
#define CPB  4                      // channels per CTA
#define CHUNK (BH * BW)             // 256 floats per frame
#define OUT_FLOATS (TT * CHUNK)     // 4608 floats = 18 KB per (n,c)

__global__ __launch_bounds__(256) void gather3d_kernel(
    const float* __restrict__ x,
    const int*   __restrict__ idx,
    float*       __restrict__ out)
{
    __shared__ __align__(128) float buf[2][OUT_FLOATS];   // 2 x 18 KB

    // blockIdx.x = cg * NN + n   (n inner for cross-n L2 plane reuse)
    int n  = blockIdx.x & (NN - 1);
    int cg = blockIdx.x >> 7;
    int c0 = cg * CPB;

    int tid = threadIdx.x;
    int j = tid & (BW - 1);
    int i = tid >> 4;

    int iy = __ldg(&idx[2 * n]);
    int ix = __ldg(&idx[2 * n + 1]);

    // zero pad frames once into BOTH buffers (stores only read smem)
    if (tid < 128) {
        const float4 z4 = make_float4(0.f, 0.f, 0.f, 0.f);
        reinterpret_cast<float4*>(buf[0])[tid] = z4;
        reinterpret_cast<float4*>(buf[1])[tid] = z4;
    }

    uint64_t pol;
    asm("createpolicy.fractional.L2::evict_first.b64 %0, 1.0;" : "=l"(pol));

    const float* src0 = x + ((c0 * TIN) * HW + (iy + i)) * HW + (ix + j);
    float*       dst0 = out + (size_t)(n * CC + c0) * OUT_FLOATS;

#pragma unroll
    for (int cl = 0; cl < CPB; ++cl) {
        float* b = buf[cl & 1];

        // gate buffer reuse: allow at most 1 outstanding bulk group
        if (cl >= 2) {
            if (tid == 0)
                asm volatile("cp.async.bulk.wait_group.read 1;" ::: "memory");
            __syncthreads();
        }

        // gather 16 time frames of channel c0+cl (16 loads in flight)
        const float* s = src0 + cl * (TIN * HW * HW);
        float v[TIN];
#pragma unroll
        for (int t = 0; t < TIN; ++t)
            v[t] = __ldg(s + t * (HW * HW));

#pragma unroll
        for (int t = 0; t < TIN; ++t)
            b[(2 + t) * CHUNK + tid] = v[t];

        __syncthreads();

        if (tid == 0) {
            asm volatile("fence.proxy.async.shared::cta;" ::: "memory");
            uint32_t sbuf;
            asm("{ .reg .u64 a; cvta.to.shared.u64 a, %1; cvt.u32.u64 %0, a; }"
                : "=r"(sbuf) : "l"(b));
            float* d = dst0 + cl * OUT_FLOATS;   // contiguous, 16B-aligned
            asm volatile(
                "cp.async.bulk.global.shared::cta.bulk_group.L2::cache_hint "
                "[%0], [%1], %2, %3;"
                :: "l"(d), "r"(sbuf), "r"((int)(OUT_FLOATS * 4)), "l"(pol)
                : "memory");
            asm volatile("cp.async.bulk.commit_group;" ::: "memory");
        }
    }

    // smem must stay live until the async engine has READ the last buffers
    if (tid == 0)
        asm volatile("cp.async.bulk.wait_group.read 0;" ::: "memory");
    __syncthreads();
}

extern "C" void kernel_launch(void* const* d_in, const int* in_sizes, int n_in,
                              void* d_out, int out_size) {
    const float* x   = (const float*)d_in[0];
    const int*   idx = (const int*)d_in[1];
    float*       out = (float*)d_out;

    gather3d_kernel<<<(CC / CPB) * NN, 256>>>(x, idx, out);  // 4096 CTAs
}

// round 17
// speedup vs baseline: 1.3575x; 1.3575x over previous
#include <cuda_runtime.h>
#include <cuda_bf16.h>
#include <cstdint>

// Gather3d: x [1, 128, 16, 128, 128] f32, active_indices [128, 2] i32 in [0,112)
// out [128, 128, 18, 16, 16] f32:
//   out[n, c, T, i, j] = (T < 2) ? 0 : x[0, c, T-2, idx_y[n]+i, idx_x[n]+j]
//
// R16: revert to R14's winning structure (one (n,c) chunk per CTA; gather ->
// smem -> single 18 KB cp.async.bulk store; overlap comes from 8 co-resident
// CTAs per SM retiring while their stores drain). Single delta vs R14:
// L2::evict_first cache hint on the bulk store, so the 302 MB write stream
// drains to DRAM without displacing the read-reuse planes that give us the
// 76 MB compulsory read floor.

#define CC   128
#define TIN  16
#define TT   18
#define HW   128
#define NN   128
#define BH   16
#define BW   16
#define CHUNK (BH * BW)            // 256 floats per frame
#define OUT_FLOATS (TT * CHUNK)    // 4608 floats = 18 KB per (n,c)

__global__ __launch_bounds__(256) void gather3d_kernel(
    const float* __restrict__ x,
    const int*   __restrict__ idx,
    float*       __restrict__ out)
{
    __shared__ __align__(128) float buf[OUT_FLOATS];   // 18 KB

    // blockIdx.x = c * NN + n  (n inner for cross-n L2 reuse of (c,t) planes)
    int n = blockIdx.x & (NN - 1);
    int c = blockIdx.x >> 7;

    int tid = threadIdx.x;
    int j = tid & (BW - 1);
    int i = tid >> 4;

    int iy = __ldg(&idx[2 * n]);
    int ix = __ldg(&idx[2 * n + 1]);

    // zero pad frames T=0,1: 512 floats = 128 float4
    if (tid < 128)
        reinterpret_cast<float4*>(buf)[tid] = make_float4(0.f, 0.f, 0.f, 0.f);

    // gather 16 time frames: 16 independent loads in flight per thread
    const float* src = x + ((c * TIN) * HW + (iy + i)) * HW + (ix + j);
    float v[TIN];
#pragma unroll
    for (int t = 0; t < TIN; ++t)
        v[t] = __ldg(src + t * (HW * HW));

    // stage into smem (stride-1 across tid -> conflict-free)
#pragma unroll
    for (int t = 0; t < TIN; ++t)
        buf[(2 + t) * CHUNK + tid] = v[t];

    __syncthreads();

    if (tid == 0) {
        asm volatile("fence.proxy.async.shared::cta;" ::: "memory");
        uint64_t pol;
        asm("createpolicy.fractional.L2::evict_first.b64 %0, 1.0;" : "=l"(pol));
        uint32_t sbuf;
        asm("{ .reg .u64 a; cvta.to.shared.u64 a, %1; cvt.u32.u64 %0, a; }"
            : "=r"(sbuf) : "l"(buf));
        float* dst = out + (size_t)(n * CC + c) * OUT_FLOATS;  // 18 KB-aligned
        asm volatile(
            "cp.async.bulk.global.shared::cta.bulk_group.L2::cache_hint "
            "[%0], [%1], %2, %3;"
            :: "l"(dst), "r"(sbuf), "r"((int)(OUT_FLOATS * 4)), "l"(pol)
            : "memory");
        asm volatile("cp.async.bulk.commit_group;" ::: "memory");
        // smem must stay live until the async engine has READ it
        asm volatile("cp.async.bulk.wait_group.read 0;" ::: "memory");
    }
}

extern "C" void kernel_launch(void* const* d_in, const int* in_sizes, int n_in,
                              void* d_out, int out_size) {
    const float* x   = (const float*)d_in[0];
    const int*   idx = (const int*)d_in[1];
    float*       out = (float*)d_out;

    gather3d_kernel<<<CC * NN, 256>>>(x, idx, out);  // 16384 CTAs
}